// round 1
// baseline (speedup 1.0000x reference)
#include <cuda_runtime.h>
#include <cuda_bf16.h>
#include <math.h>

// Problem constants
#define Bz 4
#define Sz 2048
#define Dz 1024
#define Fz 4096
#define BSz (Bz*Sz)   // 8192

// ---------------- scratch (static device globals; no allocation) ----------------
__device__ float g_ln1[(size_t)BSz * Dz];
__device__ float g_q  [(size_t)BSz * Dz];
__device__ float g_k  [(size_t)BSz * Dz];
__device__ float g_v  [(size_t)BSz * Dz];
__device__ float g_sc [(size_t)Bz * Sz * Sz];
__device__ float g_x1 [(size_t)BSz * Dz];
__device__ float g_ln2[(size_t)BSz * Dz];
__device__ float g_h  [(size_t)BSz * Fz];

// ---------------- reductions ----------------
__device__ __forceinline__ float warp_sum(float v) {
    #pragma unroll
    for (int o = 16; o > 0; o >>= 1) v += __shfl_xor_sync(0xffffffffu, v, o);
    return v;
}
__device__ __forceinline__ float warp_max(float v) {
    #pragma unroll
    for (int o = 16; o > 0; o >>= 1) v = fmaxf(v, __shfl_xor_sync(0xffffffffu, v, o));
    return v;
}

// block reduce over 256 threads (8 warps)
__device__ __forceinline__ float block_sum(float v, float* sm) {
    int wid = threadIdx.x >> 5, lid = threadIdx.x & 31;
    v = warp_sum(v);
    if (lid == 0) sm[wid] = v;
    __syncthreads();
    float r = (lid < 8) ? sm[lid] : 0.0f;
    r = warp_sum(r);
    r = __shfl_sync(0xffffffffu, r, 0);
    __syncthreads();
    return r;
}
__device__ __forceinline__ float block_max(float v, float* sm) {
    int wid = threadIdx.x >> 5, lid = threadIdx.x & 31;
    v = warp_max(v);
    if (lid == 0) sm[wid] = v;
    __syncthreads();
    float r = (lid < 8) ? sm[lid] : -INFINITY;
    r = warp_max(r);
    r = __shfl_sync(0xffffffffu, r, 0);
    __syncthreads();
    return r;
}

// ---------------- LayerNorm: one block (256 thr) per row of D=1024 ----------------
__global__ void ln_kernel(const float* __restrict__ x,
                          const float* __restrict__ gamma,
                          const float* __restrict__ beta,
                          float* __restrict__ out) {
    __shared__ float sm[8];
    size_t row = blockIdx.x;
    const float* xr = x + row * Dz;
    float* orow = out + row * Dz;
    int t = threadIdx.x;

    float v[4];
    float s = 0.f, s2 = 0.f;
    #pragma unroll
    for (int i = 0; i < 4; i++) {
        float val = xr[t + i * 256];
        v[i] = val;
        s += val; s2 += val * val;
    }
    float tot  = block_sum(s,  sm);
    float tot2 = block_sum(s2, sm);
    float mean = tot * (1.0f / Dz);
    float var  = tot2 * (1.0f / Dz) - mean * mean;
    float inv  = rsqrtf(var + 1e-5f);
    #pragma unroll
    for (int i = 0; i < 4; i++) {
        int c = t + i * 256;
        orow[c] = gamma[c] * ((v[i] - mean) * inv) + beta[c];
    }
}

// ---------------- generic tiled GEMM ----------------
// C[M,N] = alpha * A[M,K] @ op(B) (+bias) (+relu) (+res) (causal mask for scores)
// TRANSB: B given as [N,K] row-major (B^T applied)
// Batched via blockIdx.z with element strides sA/sB/sC (res shares sC).
template<bool TRANSB, bool BIAS, bool RELU, bool RES, bool CAUSAL>
__global__ void __launch_bounds__(256, 2)
gemm_kernel(const float* __restrict__ A, const float* __restrict__ B,
            float* __restrict__ C,
            const float* __restrict__ bias, const float* __restrict__ res,
            int M, int N, int K, float alpha,
            long sA, long sB, long sC)
{
    const int BM = 128, BN = 128, BK = 16;
    __shared__ float As[BK][BM + 4];
    __shared__ float Bs[BK][BN + 4];

    A += (size_t)blockIdx.z * sA;
    B += (size_t)blockIdx.z * sB;
    C += (size_t)blockIdx.z * sC;
    if (RES) res += (size_t)blockIdx.z * sC;

    int bm = blockIdx.y * BM;
    int bn = blockIdx.x * BN;
    int tid = threadIdx.x;

    if (CAUSAL && bn >= bm + BM) {
        // entire tile above the diagonal: fill with -inf, skip compute
        for (int idx = tid; idx < BM * BN; idx += 256) {
            int r = idx >> 7, c = idx & 127;
            C[(size_t)(bm + r) * N + (bn + c)] = -INFINITY;
        }
        return;
    }

    int tx = tid & 15;          // 0..15 -> 8 cols each
    int ty = tid >> 4;          // 0..15 -> 8 rows each

    float acc[8][8];
    #pragma unroll
    for (int i = 0; i < 8; i++)
        #pragma unroll
        for (int j = 0; j < 8; j++) acc[i][j] = 0.f;

    for (int kt = 0; kt < K; kt += BK) {
        // load A tile 128x16 (transposed into As[k][m])
        #pragma unroll
        for (int i = 0; i < 2; i++) {
            int id = tid * 2 + i;       // 0..511
            int r  = id >> 2;           // 0..127
            int c4 = id & 3;            // 0..3
            float4 a = *(const float4*)(A + (size_t)(bm + r) * K + kt + c4 * 4);
            As[c4 * 4 + 0][r] = a.x;
            As[c4 * 4 + 1][r] = a.y;
            As[c4 * 4 + 2][r] = a.z;
            As[c4 * 4 + 3][r] = a.w;
        }
        if (!TRANSB) {
            // B[K,N] tile 16x128
            #pragma unroll
            for (int i = 0; i < 2; i++) {
                int id = tid * 2 + i;
                int r  = id >> 5;       // 0..15
                int c4 = id & 31;       // 0..31
                float4 bv = *(const float4*)(B + (size_t)(kt + r) * N + bn + c4 * 4);
                *(float4*)&Bs[r][c4 * 4] = bv;
            }
        } else {
            // B[N,K]; Bs[k][col] = B[bn+col][kt+k]
            #pragma unroll
            for (int i = 0; i < 2; i++) {
                int id  = tid * 2 + i;
                int col = id >> 2;      // 0..127
                int c4  = id & 3;       // 0..3
                float4 bv = *(const float4*)(B + (size_t)(bn + col) * K + kt + c4 * 4);
                Bs[c4 * 4 + 0][col] = bv.x;
                Bs[c4 * 4 + 1][col] = bv.y;
                Bs[c4 * 4 + 2][col] = bv.z;
                Bs[c4 * 4 + 3][col] = bv.w;
            }
        }
        __syncthreads();

        #pragma unroll
        for (int k = 0; k < BK; k++) {
            float a[8], b[8];
            #pragma unroll
            for (int i = 0; i < 8; i++) a[i] = As[k][ty * 8 + i];
            #pragma unroll
            for (int j = 0; j < 8; j++) b[j] = Bs[k][tx * 8 + j];
            #pragma unroll
            for (int i = 0; i < 8; i++)
                #pragma unroll
                for (int j = 0; j < 8; j++)
                    acc[i][j] = fmaf(a[i], b[j], acc[i][j]);
        }
        __syncthreads();
    }

    // epilogue
    #pragma unroll
    for (int i = 0; i < 8; i++) {
        int r = bm + ty * 8 + i;
        #pragma unroll
        for (int j = 0; j < 8; j++) {
            int c = bn + tx * 8 + j;
            float v = acc[i][j] * alpha;
            if (BIAS) v += bias[c];
            if (RELU) v = fmaxf(v, 0.f);
            if (RES)  v += res[(size_t)r * N + c];
            if (CAUSAL && c > r) v = -INFINITY;
            C[(size_t)r * N + c] = v;
        }
    }
}

// ---------------- row softmax over 2048 cols ----------------
__global__ void softmax_kernel(float* __restrict__ p) {
    __shared__ float sm[8];
    size_t row = blockIdx.x;
    float* r = p + row * (size_t)Sz;
    int t = threadIdx.x;

    float v[8];
    float m = -INFINITY;
    #pragma unroll
    for (int i = 0; i < 8; i++) {
        v[i] = r[t + i * 256];
        m = fmaxf(m, v[i]);
    }
    m = block_max(m, sm);

    float s = 0.f;
    #pragma unroll
    for (int i = 0; i < 8; i++) {
        v[i] = expf(v[i] - m);   // exp(-inf)=0 handles the mask
        s += v[i];
    }
    s = block_sum(s, sm);
    float inv = 1.0f / s;
    #pragma unroll
    for (int i = 0; i < 8; i++) r[t + i * 256] = v[i] * inv;
}

// ---------------- launcher ----------------
extern "C" void kernel_launch(void* const* d_in, const int* in_sizes, int n_in,
                              void* d_out, int out_size) {
    (void)in_sizes; (void)n_in; (void)out_size;
    const float* x      = (const float*)d_in[0];
    const float* Qw     = (const float*)d_in[1];
    const float* Kw     = (const float*)d_in[2];
    const float* Vw     = (const float*)d_in[3];
    const float* w1     = (const float*)d_in[4];
    const float* b1     = (const float*)d_in[5];
    const float* w2     = (const float*)d_in[6];
    const float* b2     = (const float*)d_in[7];
    const float* gamma1 = (const float*)d_in[8];
    const float* beta1  = (const float*)d_in[9];
    const float* gamma2 = (const float*)d_in[10];
    const float* beta2  = (const float*)d_in[11];
    float* out = (float*)d_out;

    float *ln1, *q, *k, *v, *sc, *x1, *ln2, *h;
    cudaGetSymbolAddress((void**)&ln1, g_ln1);
    cudaGetSymbolAddress((void**)&q,   g_q);
    cudaGetSymbolAddress((void**)&k,   g_k);
    cudaGetSymbolAddress((void**)&v,   g_v);
    cudaGetSymbolAddress((void**)&sc,  g_sc);
    cudaGetSymbolAddress((void**)&x1,  g_x1);
    cudaGetSymbolAddress((void**)&ln2, g_ln2);
    cudaGetSymbolAddress((void**)&h,   g_h);

    const float scale = 1.0f / 32.0f;   // 1/sqrt(1024)

    // 1) LN1
    ln_kernel<<<BSz, 256>>>(x, gamma1, beta1, ln1);

    // 2) Q, K, V projections: (8192x1024) @ (1024x1024)
    {
        dim3 grid(Dz / 128, BSz / 128, 1);
        gemm_kernel<false,false,false,false,false><<<grid, 256>>>(ln1, Qw, q, nullptr, nullptr, BSz, Dz, Dz, 1.f, 0, 0, 0);
        gemm_kernel<false,false,false,false,false><<<grid, 256>>>(ln1, Kw, k, nullptr, nullptr, BSz, Dz, Dz, 1.f, 0, 0, 0);
        gemm_kernel<false,false,false,false,false><<<grid, 256>>>(ln1, Vw, v, nullptr, nullptr, BSz, Dz, Dz, 1.f, 0, 0, 0);
    }

    // 3) scores = Q @ K^T * scale, causal mask; batched over B
    {
        dim3 grid(Sz / 128, Sz / 128, Bz);
        gemm_kernel<true,false,false,false,true><<<grid, 256>>>(
            q, k, sc, nullptr, nullptr, Sz, Sz, Dz, scale,
            (long)Sz * Dz, (long)Sz * Dz, (long)Sz * Sz);
    }

    // 4) softmax over each of B*S rows (2048 cols)
    softmax_kernel<<<Bz * Sz, 256>>>(sc);

    // 5) x1 = x + P @ V; batched over B
    {
        dim3 grid(Dz / 128, Sz / 128, Bz);
        gemm_kernel<false,false,false,true,false><<<grid, 256>>>(
            sc, v, x1, nullptr, x, Sz, Dz, Sz, 1.f,
            (long)Sz * Sz, (long)Sz * Dz, (long)Sz * Dz);
    }

    // 6) LN2
    ln_kernel<<<BSz, 256>>>(x1, gamma2, beta2, ln2);

    // 7) h = relu(ln2 @ w1 + b1)
    {
        dim3 grid(Fz / 128, BSz / 128, 1);
        gemm_kernel<false,true,true,false,false><<<grid, 256>>>(ln2, w1, h, b1, nullptr, BSz, Fz, Dz, 1.f, 0, 0, 0);
    }

    // 8) out = x1 + h @ w2 + b2
    {
        dim3 grid(Dz / 128, BSz / 128, 1);
        gemm_kernel<false,true,false,true,false><<<grid, 256>>>(h, w2, out, b2, x1, BSz, Dz, Fz, 1.f, 0, 0, 0);
    }
}

// round 4
// speedup vs baseline: 2.8487x; 2.8487x over previous
#include <cuda_runtime.h>
#include <cuda_bf16.h>
#include <math.h>
#include <stdint.h>

// Problem constants
#define Bz 4
#define Sz 2048
#define Dz 1024
#define Fz 4096
#define BSz (Bz*Sz)   // 8192

// GEMM tiling (mma.sync path)
#define BM 128
#define BN 128
#define BK 32
#define TSTRIDE 40                    // padded row stride in bf16 elems (80B)
#define TILE_BYTES (128*TSTRIDE*2)    // 10240 B per plane tile
#define STAGE_BYTES (4*TILE_BYTES)    // Ah, Al, Bh, Bl
#define SMEM_TOTAL (2*STAGE_BYTES)    // 81920 B

// ---------------- scratch (static device globals; no allocation) ----------------
#define AL __align__(256)
__device__ AL __nv_bfloat16 s_ln1h[(size_t)BSz*Dz], s_ln1l[(size_t)BSz*Dz];
__device__ AL __nv_bfloat16 s_qwTh[(size_t)Dz*Dz],  s_qwTl[(size_t)Dz*Dz];
__device__ AL __nv_bfloat16 s_kwTh[(size_t)Dz*Dz],  s_kwTl[(size_t)Dz*Dz];
__device__ AL __nv_bfloat16 s_vwTh[(size_t)Dz*Dz],  s_vwTl[(size_t)Dz*Dz];
__device__ AL __nv_bfloat16 s_qh[(size_t)BSz*Dz],   s_ql[(size_t)BSz*Dz];
__device__ AL __nv_bfloat16 s_kh[(size_t)BSz*Dz],   s_kl[(size_t)BSz*Dz];
__device__ AL float         s_v [(size_t)BSz*Dz];
__device__ AL __nv_bfloat16 s_vTh[(size_t)Bz*Dz*Sz], s_vTl[(size_t)Bz*Dz*Sz];
__device__ AL float         s_sc[(size_t)Bz*Sz*Sz];
__device__ AL __nv_bfloat16 s_ph[(size_t)Bz*Sz*Sz], s_pl[(size_t)Bz*Sz*Sz];
__device__ AL float         s_x1[(size_t)BSz*Dz];
__device__ AL __nv_bfloat16 s_ln2h[(size_t)BSz*Dz], s_ln2l[(size_t)BSz*Dz];
__device__ AL __nv_bfloat16 s_w1Th[(size_t)Fz*Dz],  s_w1Tl[(size_t)Fz*Dz];
__device__ AL __nv_bfloat16 s_w2Th[(size_t)Dz*Fz],  s_w2Tl[(size_t)Dz*Fz];
__device__ AL __nv_bfloat16 s_hh[(size_t)BSz*Fz],   s_hl[(size_t)BSz*Fz];

// ---------------- PTX helpers (arch-portable: cp.async + ldmatrix + mma.sync) ----------------
__device__ __forceinline__ uint32_t smem_u32(const void* p) {
    uint32_t a;
    asm("{ .reg .u64 t; cvta.to.shared.u64 t, %1; cvt.u32.u64 %0, t; }" : "=r"(a) : "l"(p));
    return a;
}
__device__ __forceinline__ void cp16(uint32_t dst, const void* src) {
    asm volatile("cp.async.cg.shared.global [%0], [%1], 16;" :: "r"(dst), "l"(src));
}
__device__ __forceinline__ void cp_commit() { asm volatile("cp.async.commit_group;" ::: "memory"); }
__device__ __forceinline__ void cp_wait1()  { asm volatile("cp.async.wait_group 1;" ::: "memory"); }

__device__ __forceinline__ void ldm_x4(uint32_t* r, uint32_t addr) {
    asm volatile("ldmatrix.sync.aligned.m8n8.x4.shared.b16 {%0,%1,%2,%3}, [%4];"
                 : "=r"(r[0]), "=r"(r[1]), "=r"(r[2]), "=r"(r[3]) : "r"(addr));
}
__device__ __forceinline__ void mma16816(float* c, const uint32_t* a, const uint32_t* b) {
    asm volatile(
        "mma.sync.aligned.m16n8k16.row.col.f32.bf16.bf16.f32 "
        "{%0,%1,%2,%3}, {%4,%5,%6,%7}, {%8,%9}, {%0,%1,%2,%3};"
        : "+f"(c[0]), "+f"(c[1]), "+f"(c[2]), "+f"(c[3])
        : "r"(a[0]), "r"(a[1]), "r"(a[2]), "r"(a[3]), "r"(b[0]), "r"(b[1]));
}
__device__ __forceinline__ uint32_t pack_bf16x2(float a, float b) {
    __nv_bfloat16 ha = __float2bfloat16(a), hb = __float2bfloat16(b);
    return ((uint32_t)__bfloat16_as_ushort(hb) << 16) | (uint32_t)__bfloat16_as_ushort(ha);
}

// ---------------- reductions ----------------
__device__ __forceinline__ float warp_sum(float v) {
    #pragma unroll
    for (int o = 16; o > 0; o >>= 1) v += __shfl_xor_sync(0xffffffffu, v, o);
    return v;
}
__device__ __forceinline__ float warp_max(float v) {
    #pragma unroll
    for (int o = 16; o > 0; o >>= 1) v = fmaxf(v, __shfl_xor_sync(0xffffffffu, v, o));
    return v;
}
__device__ __forceinline__ float block_sum(float v, float* sm) {
    int wid = threadIdx.x >> 5, lid = threadIdx.x & 31;
    v = warp_sum(v);
    if (lid == 0) sm[wid] = v;
    __syncthreads();
    float r = (lid < 8) ? sm[lid] : 0.0f;
    r = warp_sum(r);
    r = __shfl_sync(0xffffffffu, r, 0);
    __syncthreads();
    return r;
}
__device__ __forceinline__ float block_max(float v, float* sm) {
    int wid = threadIdx.x >> 5, lid = threadIdx.x & 31;
    v = warp_max(v);
    if (lid == 0) sm[wid] = v;
    __syncthreads();
    float r = (lid < 8) ? sm[lid] : -INFINITY;
    r = warp_max(r);
    r = __shfl_sync(0xffffffffu, r, 0);
    __syncthreads();
    return r;
}

// ---------------- LN writing split planes ----------------
__global__ void ln_split_kernel(const float* __restrict__ x,
                                const float* __restrict__ gamma,
                                const float* __restrict__ beta,
                                __nv_bfloat16* __restrict__ hi,
                                __nv_bfloat16* __restrict__ lo) {
    __shared__ float sm[8];
    size_t row = blockIdx.x;
    const float* xr = x + row * Dz;
    int t = threadIdx.x;
    float v[4];
    float s = 0.f, s2 = 0.f;
    #pragma unroll
    for (int i = 0; i < 4; i++) {
        float val = xr[t + i * 256];
        v[i] = val; s += val; s2 += val * val;
    }
    float tot  = block_sum(s,  sm);
    float tot2 = block_sum(s2, sm);
    float mean = tot * (1.0f / Dz);
    float var  = tot2 * (1.0f / Dz) - mean * mean;
    float inv  = rsqrtf(var + 1e-5f);
    #pragma unroll
    for (int i = 0; i < 4; i++) {
        int c = t + i * 256;
        float y = gamma[c] * ((v[i] - mean) * inv) + beta[c];
        __nv_bfloat16 h = __float2bfloat16(y);
        hi[row * Dz + c] = h;
        lo[row * Dz + c] = __float2bfloat16(y - __bfloat162float(h));
    }
}

// ---------------- transpose + split: in fp32 [R,C] -> planes [C,R] ----------------
__global__ void transpose_split_kernel(const float* __restrict__ in,
                                       __nv_bfloat16* __restrict__ hi,
                                       __nv_bfloat16* __restrict__ lo,
                                       int R, int C, long sIn, long sOut) {
    __shared__ float t[32][33];
    in += (size_t)blockIdx.z * sIn;
    hi += (size_t)blockIdx.z * sOut;
    lo += (size_t)blockIdx.z * sOut;
    int rb = blockIdx.y * 32, cb = blockIdx.x * 32;
    int tx = threadIdx.x, ty = threadIdx.y;
    #pragma unroll
    for (int k = 0; k < 4; k++)
        t[ty + 8 * k][tx] = in[(size_t)(rb + ty + 8 * k) * C + cb + tx];
    __syncthreads();
    #pragma unroll
    for (int k = 0; k < 4; k++) {
        float v = t[tx][ty + 8 * k];
        int orow = cb + ty + 8 * k, ocol = rb + tx;
        __nv_bfloat16 h = __float2bfloat16(v);
        hi[(size_t)orow * R + ocol] = h;
        lo[(size_t)orow * R + ocol] = __float2bfloat16(v - __bfloat162float(h));
    }
}

// ---------------- causal softmax -> split probs ----------------
__global__ void softmax_split_kernel(const float* __restrict__ sc,
                                     __nv_bfloat16* __restrict__ Phi,
                                     __nv_bfloat16* __restrict__ Plo) {
    __shared__ float sm[8];
    int row = blockIdx.x;
    int r = row & (Sz - 1);
    const float* src = sc + (size_t)row * Sz;
    int t = threadIdx.x;
    float v[8];
    float m = -INFINITY;
    #pragma unroll
    for (int i = 0; i < 8; i++) {
        int c = t + i * 256;
        float val = src[c];
        val = (c <= r) ? val : -INFINITY;
        v[i] = val;
        m = fmaxf(m, val);
    }
    m = block_max(m, sm);
    float s = 0.f;
    #pragma unroll
    for (int i = 0; i < 8; i++) {
        v[i] = expf(v[i] - m);
        s += v[i];
    }
    s = block_sum(s, sm);
    float inv = 1.0f / s;
    #pragma unroll
    for (int i = 0; i < 8; i++) {
        int c = t + i * 256;
        float p = v[i] * inv;
        __nv_bfloat16 h = __float2bfloat16(p);
        Phi[(size_t)row * Sz + c] = h;
        Plo[(size_t)row * Sz + c] = __float2bfloat16(p - __bfloat162float(h));
    }
}

// ---------------- split-bf16 GEMM via mma.sync (HMMA) ----------------
// C[M,N] = alpha * sum_k A[m,k]*Bt[n,k]  (A,Bt as hi/lo bf16 planes, K-major)
// OUTM: 0 = fp32 C, 1 = split planes (Chi/Clo)
template<int OUTM, bool BIAS_, bool RELU_, bool RES_, bool CAUSAL_, bool KTRIM_>
__global__ void __launch_bounds__(256, 2)
tc_gemm(const __nv_bfloat16* __restrict__ Ahi, const __nv_bfloat16* __restrict__ Alo,
        const __nv_bfloat16* __restrict__ Bhi, const __nv_bfloat16* __restrict__ Blo,
        float* __restrict__ Cf,
        __nv_bfloat16* __restrict__ Chi, __nv_bfloat16* __restrict__ Clo,
        const float* __restrict__ bias, const float* __restrict__ res,
        int M, int N, int K, float alpha, long sA, long sB, long sC)
{
    extern __shared__ char dynsmem[];
    const int bm = blockIdx.y * BM;
    const int bn = blockIdx.x * BN;
    if (CAUSAL_ && bn >= bm + BM) return;   // fully masked tile (softmax re-masks anyway)

    const int tid  = threadIdx.x;
    const int wid  = tid >> 5;
    const int lane = tid & 31;
    const int warp_m = wid >> 1;     // 0..3  (rows, 32 each)
    const int warp_n = wid & 1;      // 0..1  (cols, 64 each)

    Ahi += (size_t)blockIdx.z * sA;  Alo += (size_t)blockIdx.z * sA;
    Bhi += (size_t)blockIdx.z * sB;  Blo += (size_t)blockIdx.z * sB;
    if (OUTM == 0) Cf += (size_t)blockIdx.z * sC;
    else { Chi += (size_t)blockIdx.z * sC; Clo += (size_t)blockIdx.z * sC; }
    if (RES_) res += (size_t)blockIdx.z * sC;

    const uint32_t smem_base = smem_u32(dynsmem);

    const int kmax = KTRIM_ ? min(K, bm + BM) : K;
    const int nst  = kmax >> 5;      // BK=32

    // per-stage cp.async: 2048 chunks of 16B (A h/l + B h/l), 8 per thread
    auto issue_loads = [&](int s) {
        uint32_t sb = smem_base + (uint32_t)(s & 1) * STAGE_BYTES;
        int kt = s * BK;
        #pragma unroll
        for (int i = 0; i < 4; i++) {            // A: 1024 chunks
            int id = i * 256 + tid;              // 0..1023
            const __nv_bfloat16* src = (id < 512) ? Ahi : Alo;
            uint32_t off = (id < 512) ? 0u : TILE_BYTES;
            int r  = (id >> 2) & 127;
            int c4 = id & 3;
            cp16(sb + off + (uint32_t)(r * TSTRIDE + c4 * 8) * 2,
                 src + (size_t)(bm + r) * K + kt + c4 * 8);
        }
        #pragma unroll
        for (int i = 0; i < 4; i++) {            // B: 1024 chunks
            int id = i * 256 + tid;
            const __nv_bfloat16* src = (id < 512) ? Bhi : Blo;
            uint32_t off = 2u * TILE_BYTES + ((id < 512) ? 0u : TILE_BYTES);
            int r  = (id >> 2) & 127;
            int c4 = id & 3;
            cp16(sb + off + (uint32_t)(r * TSTRIDE + c4 * 8) * 2,
                 src + (size_t)(bn + r) * K + kt + c4 * 8);
        }
    };

    float acc[2][8][4];
    #pragma unroll
    for (int i = 0; i < 2; i++)
        #pragma unroll
        for (int j = 0; j < 8; j++)
            #pragma unroll
            for (int k = 0; k < 4; k++) acc[i][j][k] = 0.f;

    issue_loads(0); cp_commit();
    if (nst > 1) issue_loads(1);
    cp_commit();

    for (int s = 0; s < nst; s++) {
        cp_wait1();
        __syncthreads();

        uint32_t sb = smem_base + (uint32_t)(s & 1) * STAGE_BYTES;
        uint32_t aH = sb, aL = sb + TILE_BYTES;
        uint32_t bH = sb + 2u * TILE_BYTES, bL = sb + 3u * TILE_BYTES;

        #pragma unroll
        for (int k16 = 0; k16 < BK; k16 += 16) {
            // A fragments: 2 m16 chunks x {hi,lo}
            uint32_t ah[2][4], al[2][4];
            #pragma unroll
            for (int mi = 0; mi < 2; mi++) {
                uint32_t arow = (uint32_t)(warp_m * 32 + mi * 16 + (lane & 15));
                uint32_t aoff = (arow * TSTRIDE + (uint32_t)(k16 + (lane >> 4) * 8)) * 2;
                ldm_x4(ah[mi], aH + aoff);
                ldm_x4(al[mi], aL + aoff);
            }
            // B: 4 n16 chunks; per chunk x4 -> regs [sub0:b0,b1, sub1:b0,b1]
            #pragma unroll
            for (int j = 0; j < 4; j++) {
                uint32_t brow = (uint32_t)(warp_n * 64 + j * 16 + ((lane >> 4) * 8) + (lane & 7));
                uint32_t boff = (brow * TSTRIDE + (uint32_t)(k16 + ((lane >> 3) & 1) * 8)) * 2;
                uint32_t bh[4], bl[4];
                ldm_x4(bh, bH + boff);
                ldm_x4(bl, bL + boff);
                #pragma unroll
                for (int sub = 0; sub < 2; sub++) {
                    int ni = j * 2 + sub;
                    #pragma unroll
                    for (int mi = 0; mi < 2; mi++) {
                        mma16816(acc[mi][ni], ah[mi], bh + sub * 2);  // hi*hi
                        mma16816(acc[mi][ni], ah[mi], bl + sub * 2);  // hi*lo
                        mma16816(acc[mi][ni], al[mi], bh + sub * 2);  // lo*hi
                    }
                }
            }
        }
        __syncthreads();
        if (s + 2 < nst) issue_loads(s + 2);
        cp_commit();
    }

    // ---------------- epilogue from register accumulators ----------------
    const int g = lane >> 2, t4 = lane & 3;
    #pragma unroll
    for (int mi = 0; mi < 2; mi++) {
        #pragma unroll
        for (int ni = 0; ni < 8; ni++) {
            int col = bn + warp_n * 64 + ni * 8 + t4 * 2;
            #pragma unroll
            for (int half = 0; half < 2; half++) {
                int row = bm + warp_m * 32 + mi * 16 + g + half * 8;
                float v0 = acc[mi][ni][half * 2 + 0] * alpha;
                float v1 = acc[mi][ni][half * 2 + 1] * alpha;
                if (BIAS_) { v0 += bias[col]; v1 += bias[col + 1]; }
                if (RELU_) { v0 = fmaxf(v0, 0.f); v1 = fmaxf(v1, 0.f); }
                if (RES_) {
                    float2 rv = *(const float2*)(res + (size_t)row * N + col);
                    v0 += rv.x; v1 += rv.y;
                }
                if (OUTM == 0) {
                    float2 o; o.x = v0; o.y = v1;
                    *(float2*)(Cf + (size_t)row * N + col) = o;
                } else {
                    uint32_t hp = pack_bf16x2(v0, v1);
                    float l0 = v0 - __bfloat162float(__float2bfloat16(v0));
                    float l1 = v1 - __bfloat162float(__float2bfloat16(v1));
                    uint32_t lp = pack_bf16x2(l0, l1);
                    *(uint32_t*)(Chi + (size_t)row * N + col) = hp;
                    *(uint32_t*)(Clo + (size_t)row * N + col) = lp;
                }
            }
        }
    }
}

// ---------------- launcher ----------------
extern "C" void kernel_launch(void* const* d_in, const int* in_sizes, int n_in,
                              void* d_out, int out_size) {
    (void)in_sizes; (void)n_in; (void)out_size;
    const float* x      = (const float*)d_in[0];
    const float* Qw     = (const float*)d_in[1];
    const float* Kw     = (const float*)d_in[2];
    const float* Vw     = (const float*)d_in[3];
    const float* w1     = (const float*)d_in[4];
    const float* b1     = (const float*)d_in[5];
    const float* w2     = (const float*)d_in[6];
    const float* b2     = (const float*)d_in[7];
    const float* gamma1 = (const float*)d_in[8];
    const float* beta1  = (const float*)d_in[9];
    const float* gamma2 = (const float*)d_in[10];
    const float* beta2  = (const float*)d_in[11];
    float* out = (float*)d_out;

    __nv_bfloat16 *ln1h,*ln1l,*qwTh,*qwTl,*kwTh,*kwTl,*vwTh,*vwTl;
    __nv_bfloat16 *qh,*ql,*kh,*kl,*vTh,*vTl,*ph,*pl,*ln2h,*ln2l;
    __nv_bfloat16 *w1Th,*w1Tl,*w2Th,*w2Tl,*hh,*hl;
    float *vf,*sc,*x1;
    cudaGetSymbolAddress((void**)&ln1h, s_ln1h); cudaGetSymbolAddress((void**)&ln1l, s_ln1l);
    cudaGetSymbolAddress((void**)&qwTh, s_qwTh); cudaGetSymbolAddress((void**)&qwTl, s_qwTl);
    cudaGetSymbolAddress((void**)&kwTh, s_kwTh); cudaGetSymbolAddress((void**)&kwTl, s_kwTl);
    cudaGetSymbolAddress((void**)&vwTh, s_vwTh); cudaGetSymbolAddress((void**)&vwTl, s_vwTl);
    cudaGetSymbolAddress((void**)&qh, s_qh);     cudaGetSymbolAddress((void**)&ql, s_ql);
    cudaGetSymbolAddress((void**)&kh, s_kh);     cudaGetSymbolAddress((void**)&kl, s_kl);
    cudaGetSymbolAddress((void**)&vf, s_v);
    cudaGetSymbolAddress((void**)&vTh, s_vTh);   cudaGetSymbolAddress((void**)&vTl, s_vTl);
    cudaGetSymbolAddress((void**)&sc, s_sc);
    cudaGetSymbolAddress((void**)&ph, s_ph);     cudaGetSymbolAddress((void**)&pl, s_pl);
    cudaGetSymbolAddress((void**)&x1, s_x1);
    cudaGetSymbolAddress((void**)&ln2h, s_ln2h); cudaGetSymbolAddress((void**)&ln2l, s_ln2l);
    cudaGetSymbolAddress((void**)&w1Th, s_w1Th); cudaGetSymbolAddress((void**)&w1Tl, s_w1Tl);
    cudaGetSymbolAddress((void**)&w2Th, s_w2Th); cudaGetSymbolAddress((void**)&w2Tl, s_w2Tl);
    cudaGetSymbolAddress((void**)&hh, s_hh);     cudaGetSymbolAddress((void**)&hl, s_hl);

    cudaFuncSetAttribute(tc_gemm<1,false,false,false,false,false>, cudaFuncAttributeMaxDynamicSharedMemorySize, SMEM_TOTAL);
    cudaFuncSetAttribute(tc_gemm<0,false,false,false,false,false>, cudaFuncAttributeMaxDynamicSharedMemorySize, SMEM_TOTAL);
    cudaFuncSetAttribute(tc_gemm<0,false,false,false,true ,false>, cudaFuncAttributeMaxDynamicSharedMemorySize, SMEM_TOTAL);
    cudaFuncSetAttribute(tc_gemm<0,false,false,true ,false,true >, cudaFuncAttributeMaxDynamicSharedMemorySize, SMEM_TOTAL);
    cudaFuncSetAttribute(tc_gemm<1,true ,true ,false,false,false>, cudaFuncAttributeMaxDynamicSharedMemorySize, SMEM_TOTAL);
    cudaFuncSetAttribute(tc_gemm<0,true ,false,true ,false,false>, cudaFuncAttributeMaxDynamicSharedMemorySize, SMEM_TOTAL);

    const float scale = 1.0f / 32.0f;

    // 1) LN1 -> split planes
    ln_split_kernel<<<BSz, 256>>>(x, gamma1, beta1, ln1h, ln1l);

    // 2) weight transposes -> split planes
    {
        dim3 blk(32, 8);
        transpose_split_kernel<<<dim3(Dz/32, Dz/32, 1), blk>>>(Qw, qwTh, qwTl, Dz, Dz, 0, 0);
        transpose_split_kernel<<<dim3(Dz/32, Dz/32, 1), blk>>>(Kw, kwTh, kwTl, Dz, Dz, 0, 0);
        transpose_split_kernel<<<dim3(Dz/32, Dz/32, 1), blk>>>(Vw, vwTh, vwTl, Dz, Dz, 0, 0);
        transpose_split_kernel<<<dim3(Fz/32, Dz/32, 1), blk>>>(w1, w1Th, w1Tl, Dz, Fz, 0, 0);
        transpose_split_kernel<<<dim3(Dz/32, Fz/32, 1), blk>>>(w2, w2Th, w2Tl, Fz, Dz, 0, 0);
    }

    // 3) Q, K projections -> split planes; V -> fp32
    {
        dim3 grid(Dz/BN, BSz/BM, 1);
        tc_gemm<1,false,false,false,false,false><<<grid, 256, SMEM_TOTAL>>>(
            ln1h, ln1l, qwTh, qwTl, nullptr, qh, ql, nullptr, nullptr,
            BSz, Dz, Dz, 1.f, 0, 0, 0);
        tc_gemm<1,false,false,false,false,false><<<grid, 256, SMEM_TOTAL>>>(
            ln1h, ln1l, kwTh, kwTl, nullptr, kh, kl, nullptr, nullptr,
            BSz, Dz, Dz, 1.f, 0, 0, 0);
        tc_gemm<0,false,false,false,false,false><<<grid, 256, SMEM_TOTAL>>>(
            ln1h, ln1l, vwTh, vwTl, vf, nullptr, nullptr, nullptr, nullptr,
            BSz, Dz, Dz, 1.f, 0, 0, 0);
    }

    // 4) V^T split planes (per batch [D,S])
    {
        dim3 blk(32, 8);
        transpose_split_kernel<<<dim3(Dz/32, Sz/32, Bz), blk>>>(
            vf, vTh, vTl, Sz, Dz, (long)Sz*Dz, (long)Dz*Sz);
    }

    // 5) scores = Q@K^T * scale (causal tile-skip), fp32 out
    {
        dim3 grid(Sz/BN, Sz/BM, Bz);
        tc_gemm<0,false,false,false,true,false><<<grid, 256, SMEM_TOTAL>>>(
            qh, ql, kh, kl, sc, nullptr, nullptr, nullptr, nullptr,
            Sz, Sz, Dz, scale, (long)Sz*Dz, (long)Sz*Dz, (long)Sz*Sz);
    }

    // 6) causal softmax -> split probs
    softmax_split_kernel<<<BSz, 256>>>(sc, ph, pl);

    // 7) x1 = x + P@V   (K trimmed by causality)
    {
        dim3 grid(Dz/BN, Sz/BM, Bz);
        tc_gemm<0,false,false,true,false,true><<<grid, 256, SMEM_TOTAL>>>(
            ph, pl, vTh, vTl, x1, nullptr, nullptr, nullptr, x,
            Sz, Dz, Sz, 1.f, (long)Sz*Sz, (long)Dz*Sz, (long)Sz*Dz);
    }

    // 8) LN2 -> split planes
    ln_split_kernel<<<BSz, 256>>>(x1, gamma2, beta2, ln2h, ln2l);

    // 9) h = relu(ln2 @ w1 + b1) -> split planes
    {
        dim3 grid(Fz/BN, BSz/BM, 1);
        tc_gemm<1,true,true,false,false,false><<<grid, 256, SMEM_TOTAL>>>(
            ln2h, ln2l, w1Th, w1Tl, nullptr, hh, hl, b1, nullptr,
            BSz, Fz, Dz, 1.f, 0, 0, 0);
    }

    // 10) out = x1 + h @ w2 + b2
    {
        dim3 grid(Dz/BN, BSz/BM, 1);
        tc_gemm<0,true,false,true,false,false><<<grid, 256, SMEM_TOTAL>>>(
            hh, hl, w2Th, w2Tl, out, nullptr, nullptr, b2, x1,
            BSz, Dz, Fz, 1.f, 0, 0, 0);
    }
}